// round 9
// baseline (speedup 1.0000x reference)
#include <cuda_runtime.h>
#include <cstdint>

#define NPTS 32768
#define DD   512
#define KC   4096
#define LC   3
#define NQ   ((size_t)NPTS * DD)
#define NIDX ((size_t)NPTS * LC)

#define MT 128
#define NTILES 32               // 4096 / 128 cols
#define NCHUNK 128              // 32 tiles * 4 k-chunks
#define MARGIN 8.0f
#define CAND_CAP 32

// smem: A 64KB | B 2x16KB
#define OFF_B 65536
#define SMEM_TOTAL 98304

__device__ float   g_resid[NPTS * DD];
__device__ int8_t  g_ai8[NPTS * DD];
__device__ float   g_sa[NPTS];
__device__ int8_t  g_bi8[LC * KC * DD];
__device__ float   g_sb[LC * KC];
__device__ float   g_c[LC * KC];
__device__ int2    g_cand[NPTS * CAND_CAP];
__device__ int     g_ccnt[NPTS];
__device__ int     g_counts[LC * KC];
__device__ double  g_commit;
__device__ float   g_perp[LC];

__device__ __forceinline__ uint32_t smem_u32(const void* p) {
    uint32_t a;
    asm("{ .reg .u64 t; cvta.to.shared.u64 t, %1; cvt.u32.u64 %0, t; }" : "=r"(a) : "l"(p));
    return a;
}
#define CP_ASYNC16(dst, src) asm volatile("cp.async.cg.shared.global [%0], [%1], 16;" :: "r"(dst), "l"(src))
#define CP_COMMIT() asm volatile("cp.async.commit_group;" ::: "memory")
#define CP_WAIT0()  asm volatile("cp.async.wait_group 0;" ::: "memory")

__device__ __forceinline__ void ldmat4(uint32_t* r, uint32_t addr) {
    asm volatile("ldmatrix.sync.aligned.m8n8.x4.shared.b16 {%0,%1,%2,%3}, [%4];"
        : "=r"(r[0]), "=r"(r[1]), "=r"(r[2]), "=r"(r[3]) : "r"(addr));
}
__device__ __forceinline__ void mma_s8(int* d, const uint32_t* a, const uint32_t* b) {
    asm volatile("mma.sync.aligned.m16n8k32.row.col.s32.s8.s8.s32 "
        "{%0,%1,%2,%3}, {%4,%5,%6,%7}, {%8,%9}, {%0,%1,%2,%3};"
        : "+r"(d[0]), "+r"(d[1]), "+r"(d[2]), "+r"(d[3])
        : "r"(a[0]), "r"(a[1]), "r"(a[2]), "r"(a[3]), "r"(b[0]), "r"(b[1]));
}

__global__ void init_kernel() {
    int i = blockIdx.x * blockDim.x + threadIdx.x;
    if (i < LC * KC) g_counts[i] = 0;
    if (i < NPTS) g_ccnt[i] = 0;
    if (i == 0) g_commit = 0.0;
}

__global__ void quant_z_kernel(const float* __restrict__ z) {
    int row = (blockIdx.x * blockDim.x + threadIdx.x) >> 5;
    int lane = threadIdx.x & 31;
    if (row >= NPTS) return;
    const float4* src = (const float4*)(z + (size_t)row * DD);
    float a[16], amax = 0.f;
    #pragma unroll
    for (int j = 0; j < 4; j++) {
        float4 v = src[j * 32 + lane];
        a[j*4+0] = v.x; a[j*4+1] = v.y; a[j*4+2] = v.z; a[j*4+3] = v.w;
        amax = fmaxf(amax, fmaxf(fmaxf(fabsf(v.x), fabsf(v.y)), fmaxf(fabsf(v.z), fabsf(v.w))));
    }
    #pragma unroll
    for (int o = 16; o; o >>= 1) amax = fmaxf(amax, __shfl_xor_sync(0xffffffffu, amax, o));
    amax = fmaxf(amax, 1e-30f);
    float inv_s = 127.0f / amax;
    #pragma unroll
    for (int j = 0; j < 4; j++) {
        char4 q;
        q.x = (char)__float2int_rn(a[j*4+0] * inv_s);
        q.y = (char)__float2int_rn(a[j*4+1] * inv_s);
        q.z = (char)__float2int_rn(a[j*4+2] * inv_s);
        q.w = (char)__float2int_rn(a[j*4+3] * inv_s);
        *(char4*)(g_ai8 + (size_t)row * DD + (j * 32 + lane) * 4) = q;
    }
    if (lane == 0) g_sa[row] = amax * (1.0f / 127.0f);
}

__global__ void quant_cb_kernel(const float* __restrict__ cb) {
    int row = (blockIdx.x * blockDim.x + threadIdx.x) >> 5;
    int lane = threadIdx.x & 31;
    if (row >= LC * KC) return;
    const float4* src = (const float4*)(cb + (size_t)row * DD);
    float a[16], amax = 0.f, ss = 0.f;
    #pragma unroll
    for (int j = 0; j < 4; j++) {
        float4 v = src[j * 32 + lane];
        a[j*4+0] = v.x; a[j*4+1] = v.y; a[j*4+2] = v.z; a[j*4+3] = v.w;
        amax = fmaxf(amax, fmaxf(fmaxf(fabsf(v.x), fabsf(v.y)), fmaxf(fabsf(v.z), fabsf(v.w))));
        ss += v.x*v.x + v.y*v.y + v.z*v.z + v.w*v.w;
    }
    #pragma unroll
    for (int o = 16; o; o >>= 1) {
        amax = fmaxf(amax, __shfl_xor_sync(0xffffffffu, amax, o));
        ss += __shfl_xor_sync(0xffffffffu, ss, o);
    }
    amax = fmaxf(amax, 1e-30f);
    float inv_s = 127.0f / amax;
    #pragma unroll
    for (int j = 0; j < 4; j++) {
        char4 q;
        q.x = (char)__float2int_rn(a[j*4+0] * inv_s);
        q.y = (char)__float2int_rn(a[j*4+1] * inv_s);
        q.z = (char)__float2int_rn(a[j*4+2] * inv_s);
        q.w = (char)__float2int_rn(a[j*4+3] * inv_s);
        *(char4*)(g_bi8 + (size_t)row * DD + (j * 32 + lane) * 4) = q;
    }
    if (lane == 0) { g_sb[row] = amax * (1.0f / 127.0f); g_c[row] = 0.5f * ss; }
}

// ---- int8 GEMM: CTA = 128 rows x ALL 4096 cols, A resident in smem,
//      register epilogue appends in-margin candidates ----
__global__ __launch_bounds__(256, 2) void gemm_kernel(int layer) {
    extern __shared__ char smem[];
    uint32_t sb = smem_u32(smem);
    int tid = threadIdx.x, wid = tid >> 5, lane = tid & 31;
    int warp_m = wid >> 2, warp_n = wid & 3;     // 2x4 warp grid, 64x32 warp tile
    int m0 = blockIdx.x * MT;
    const int8_t* __restrict__ A = g_ai8;
    const int8_t* __restrict__ B = g_bi8 + (size_t)layer * KC * DD;
    const float* __restrict__ cl = g_c + layer * KC;
    const float* __restrict__ sbl = g_sb + layer * KC;

    // ---- A tile load (once): 4096 units of 16B; swizzled for 512B rows ----
    #pragma unroll
    for (int i = 0; i < 16; i++) {
        int f = tid + i * 256;              // 0..4095
        int r = f >> 5, v = f & 31;
        uint32_t d = (uint32_t)(r * 512 + (((v & 24) | ((v ^ r) & 7)) << 4));
        CP_ASYNC16(sb + d, A + (size_t)(m0 + r) * DD + v * 16);
    }
    CP_COMMIT();

    // ---- B chunk loader precompute: 1024 units per 16KB chunk ----
    const int8_t* bsrc[4]; uint32_t bdst[4];
    #pragma unroll
    for (int i = 0; i < 4; i++) {
        int f = tid + i * 256;              // 0..1023
        int r = f >> 3, v = f & 7;
        bsrc[i] = B + (size_t)r * DD + v * 16;
        bdst[i] = (uint32_t)(r * 128 + ((v ^ (r & 7)) << 4));
    }
    auto load_b = [&](int buf, int j) {
        int off = (j >> 2) * (128 * DD) + (j & 3) * 128;
        uint32_t base = sb + OFF_B + buf * 16384;
        #pragma unroll
        for (int i = 0; i < 4; i++) CP_ASYNC16(base + bdst[i], bsrc[i] + off);
    };
    load_b(0, 0); CP_COMMIT();

    // ---- fragment addressing ----
    int rm = lane & 7;
    int aU = lane >> 4, bU = (lane >> 3) & 1;
    uint32_t aOff[4], bOff[2];
    #pragma unroll
    for (int mi = 0; mi < 4; mi++) aOff[mi] = (uint32_t)((warp_m * 64 + mi * 16 + (lane & 15)) * 512);
    #pragma unroll
    for (int nh = 0; nh < 2; nh++) bOff[nh] = (uint32_t)((warp_n * 32 + nh * 16 + (lane & 7) + ((lane >> 4) << 3)) * 128);

    int acc[4][4][4];
    #pragma unroll
    for (int mi = 0; mi < 4; mi++)
        #pragma unroll
        for (int ni = 0; ni < 4; ni++)
            #pragma unroll
            for (int e = 0; e < 4; e++) acc[mi][ni][e] = 0;

    float runmax[8];
    #pragma unroll
    for (int s = 0; s < 8; s++) runmax[s] = -3.0e38f;

    for (int j = 0; j < NCHUNK; j++) {
        CP_WAIT0();
        __syncthreads();
        if (j + 1 < NCHUNK) load_b((j + 1) & 1, j + 1);
        CP_COMMIT();
        uint32_t aC = sb + (uint32_t)((j & 3) * 128);
        uint32_t bB = sb + OFF_B + (uint32_t)((j & 1) * 16384);
        #pragma unroll
        for (int kk = 0; kk < 4; kk++) {
            uint32_t af[4][4], bf[2][4];
            int wA = kk * 2 + aU, wB = kk * 2 + bU;
            #pragma unroll
            for (int mi = 0; mi < 4; mi++)
                ldmat4(af[mi], aC + aOff[mi] + (uint32_t)(((wA ^ rm) & 7) << 4));
            #pragma unroll
            for (int nh = 0; nh < 2; nh++)
                ldmat4(bf[nh], bB + bOff[nh] + (uint32_t)(((wB ^ rm) & 7) << 4));
            #pragma unroll
            for (int mi = 0; mi < 4; mi++) {
                mma_s8(acc[mi][0], af[mi], &bf[0][0]);
                mma_s8(acc[mi][1], af[mi], &bf[0][2]);
                mma_s8(acc[mi][2], af[mi], &bf[1][0]);
                mma_s8(acc[mi][3], af[mi], &bf[1][2]);
            }
        }
        if ((j & 3) == 3) {
            // ---- register epilogue for tile t ----
            int t = j >> 2;
            int cb0 = t * 128 + warp_n * 32 + (lane & 3) * 2;
            float2 sbv[4], csv[4];
            #pragma unroll
            for (int ni = 0; ni < 4; ni++) {
                sbv[ni] = __ldg((const float2*)(sbl + cb0 + ni * 8));
                csv[ni] = __ldg((const float2*)(cl + cb0 + ni * 8));
            }
            float sar[8], tmax[8];
            #pragma unroll
            for (int s = 0; s < 8; s++) {
                sar[s] = __ldg(&g_sa[m0 + warp_m * 64 + (s >> 1) * 16 + (lane >> 2) + (s & 1) * 8]);
                tmax[s] = -3.0e38f;
            }
            #pragma unroll
            for (int mi = 0; mi < 4; mi++)
                #pragma unroll
                for (int ni = 0; ni < 4; ni++)
                    #pragma unroll
                    for (int e = 0; e < 4; e++) {
                        int s = mi * 2 + (e >> 1);
                        float sbp = (e & 1) ? sbv[ni].y : sbv[ni].x;
                        float csp = (e & 1) ? csv[ni].y : csv[ni].x;
                        float sc = fmaf(sar[s] * sbp, (float)acc[mi][ni][e], -csp);
                        acc[mi][ni][e] = __float_as_int(sc);
                        tmax[s] = fmaxf(tmax[s], sc);
                    }
            #pragma unroll
            for (int s = 0; s < 8; s++) {
                tmax[s] = fmaxf(tmax[s], __shfl_xor_sync(0xffffffffu, tmax[s], 1));
                tmax[s] = fmaxf(tmax[s], __shfl_xor_sync(0xffffffffu, tmax[s], 2));
                runmax[s] = fmaxf(runmax[s], tmax[s]);
            }
            #pragma unroll
            for (int mi = 0; mi < 4; mi++)
                #pragma unroll
                for (int ni = 0; ni < 4; ni++)
                    #pragma unroll
                    for (int e = 0; e < 4; e++) {
                        int s = mi * 2 + (e >> 1);
                        float sc = __int_as_float(acc[mi][ni][e]);
                        if (sc >= runmax[s] - MARGIN) {
                            int row = m0 + warp_m * 64 + mi * 16 + (lane >> 2) + (e >> 1) * 8;
                            int col = cb0 + ni * 8 + (e & 1);
                            int slot = atomicAdd(&g_ccnt[row], 1);
                            if (slot < CAND_CAP)
                                g_cand[row * CAND_CAP + slot] = make_int2(col, __float_as_int(sc));
                        }
                        acc[mi][ni][e] = 0;
                    }
        }
    }
}

// ---- fused exact re-rank + assign + next-layer quantize (warp per row) ----
template <bool LAST>
__global__ __launch_bounds__(128) void rerank_assign_kernel(
    const float* __restrict__ z, const float* __restrict__ cb,
    float* __restrict__ out_q, float* __restrict__ out_idx, int layer)
{
    int warp = (blockIdx.x * blockDim.x + threadIdx.x) >> 5;
    int lane = threadIdx.x & 31;
    if (warp >= NPTS) return;
    int row = warp;
    const float* Ar = (layer == 0) ? z + (size_t)row * DD : g_resid + (size_t)row * DD;
    const float* El = cb + (size_t)layer * KC * DD;
    const float* cl = g_c + layer * KC;

    int cnt = g_ccnt[row];
    if (lane == 0) g_ccnt[row] = 0;    // reset for next layer

    float a[16];
    #pragma unroll
    for (int j = 0; j < 4; j++) {
        float4 v = ((const float4*)Ar)[j * 32 + lane];
        a[j*4+0] = v.x; a[j*4+1] = v.y; a[j*4+2] = v.z; a[j*4+3] = v.w;
    }

    float bs = -3.0e38f; int bi = 0x7fffffff;
    auto eval = [&](int k) {
        const float4* E4 = (const float4*)(El + (size_t)k * DD);
        float s = 0.f;
        #pragma unroll
        for (int j = 0; j < 4; j++) {
            float4 e = E4[j * 32 + lane];
            s = fmaf(a[j*4+0], e.x, s); s = fmaf(a[j*4+1], e.y, s);
            s = fmaf(a[j*4+2], e.z, s); s = fmaf(a[j*4+3], e.w, s);
        }
        #pragma unroll
        for (int o = 16; o; o >>= 1) s += __shfl_xor_sync(0xffffffffu, s, o);
        s -= cl[k];
        if (s > bs || (s == bs && k < bi)) { bs = s; bi = k; }
    };

    if (cnt > CAND_CAP) {
        for (int k = 0; k < KC; k++) eval(k);
    } else {
        int2 cd = (lane < cnt) ? g_cand[row * CAND_CAP + lane]
                               : make_int2(0, (int)0xff800000u);
        float sc = __int_as_float(cd.y);
        float cmax = sc;
        #pragma unroll
        for (int o = 16; o; o >>= 1) cmax = fmaxf(cmax, __shfl_xor_sync(0xffffffffu, cmax, o));
        float thr = cmax - MARGIN;
        unsigned m = __ballot_sync(0xffffffffu, sc >= thr);
        if (__popc(m) == 1) {
            bi = __shfl_sync(0xffffffffu, cd.x, __ffs(m) - 1);
        } else {
            while (m) {
                int t = __ffs(m) - 1; m &= m - 1;
                eval(__shfl_sync(0xffffffffu, cd.x, t));
            }
        }
    }

    if (lane == 0) {
        out_idx[(size_t)row * LC + layer] = (float)bi;
        atomicAdd(&g_counts[layer * KC + bi], 1);
    }
    const float4* E4 = (const float4*)(El + (size_t)bi * DD);
    float csum = 0.f;
    float rn[16], amax = 0.f;
    #pragma unroll
    for (int j = 0; j < 4; j++) {
        float4 e = E4[j * 32 + lane];
        rn[j*4+0] = a[j*4+0] - e.x; rn[j*4+1] = a[j*4+1] - e.y;
        rn[j*4+2] = a[j*4+2] - e.z; rn[j*4+3] = a[j*4+3] - e.w;
        #pragma unroll
        for (int e2 = 0; e2 < 4; e2++) {
            csum += rn[j*4+e2] * rn[j*4+e2];
            amax = fmaxf(amax, fabsf(rn[j*4+e2]));
        }
        if (LAST) {
            float4 zv = ((const float4*)(z + (size_t)row * DD))[j * 32 + lane];
            ((float4*)(out_q + (size_t)row * DD))[j * 32 + lane] =
                make_float4(zv.x - rn[j*4+0], zv.y - rn[j*4+1], zv.z - rn[j*4+2], zv.w - rn[j*4+3]);
        } else {
            ((float4*)(g_resid + (size_t)row * DD))[j * 32 + lane] =
                make_float4(rn[j*4+0], rn[j*4+1], rn[j*4+2], rn[j*4+3]);
        }
    }
    if (!LAST) {
        #pragma unroll
        for (int o = 16; o; o >>= 1) amax = fmaxf(amax, __shfl_xor_sync(0xffffffffu, amax, o));
        amax = fmaxf(amax, 1e-30f);
        float inv_s = 127.0f / amax;
        #pragma unroll
        for (int j = 0; j < 4; j++) {
            char4 q;
            q.x = (char)__float2int_rn(rn[j*4+0] * inv_s);
            q.y = (char)__float2int_rn(rn[j*4+1] * inv_s);
            q.z = (char)__float2int_rn(rn[j*4+2] * inv_s);
            q.w = (char)__float2int_rn(rn[j*4+3] * inv_s);
            *(char4*)(g_ai8 + (size_t)row * DD + (j * 32 + lane) * 4) = q;
        }
        if (lane == 0) g_sa[row] = amax * (1.0f / 127.0f);
    }
    #pragma unroll
    for (int o = 16; o; o >>= 1) csum += __shfl_down_sync(0xffffffffu, csum, o);
    if (lane == 0) atomicAdd(&g_commit, (double)csum);
}

__global__ void perp_kernel() {
    int l = blockIdx.x, t = threadIdx.x;
    float local = 0.f;
    for (int k = t; k < KC; k += 256) {
        float p = (float)g_counts[l * KC + k] * (1.0f / (float)NPTS);
        local += p * logf(p + 1e-10f);
    }
    #pragma unroll
    for (int o = 16; o; o >>= 1) local += __shfl_down_sync(0xffffffffu, local, o);
    __shared__ float red[8];
    if ((t & 31) == 0) red[t >> 5] = local;
    __syncthreads();
    if (t == 0) {
        float s = 0.f;
        #pragma unroll
        for (int i = 0; i < 8; i++) s += red[i];
        g_perp[l] = expf(-s);
    }
}
__global__ void final_kernel(float* __restrict__ out_sc) {
    out_sc[0] = (float)(g_commit * (0.25 / (double)NQ));
    out_sc[1] = (g_perp[0] + g_perp[1] + g_perp[2]) * (1.0f / 3.0f);
}

extern "C" void kernel_launch(void* const* d_in, const int* in_sizes, int n_in,
                              void* d_out, int out_size)
{
    const float* z  = (const float*)d_in[0];
    const float* cb = (const float*)d_in[1];
    float* out = (float*)d_out;
    float* out_q   = out;
    float* out_idx = out + NQ;
    float* out_sc  = out_idx + NIDX;

    cudaFuncSetAttribute(gemm_kernel, cudaFuncAttributeMaxDynamicSharedMemorySize, SMEM_TOTAL);

    init_kernel<<<160, 256>>>();
    quant_z_kernel<<<NPTS / 8, 256>>>(z);
    quant_cb_kernel<<<(LC * KC) / 8, 256>>>(cb);

    for (int l = 0; l < LC; l++) {
        gemm_kernel<<<NPTS / MT, 256, SMEM_TOTAL>>>(l);
        if (l < LC - 1)
            rerank_assign_kernel<false><<<NPTS / 4, 128>>>(z, cb, out_q, out_idx, l);
        else
            rerank_assign_kernel<true><<<NPTS / 4, 128>>>(z, cb, out_q, out_idx, l);
    }
    perp_kernel<<<LC, 256>>>();
    final_kernel<<<1, 1>>>(out_sc);
}

// round 10
// speedup vs baseline: 13.8765x; 13.8765x over previous
#include <cuda_runtime.h>
#include <cstdint>

#define NPTS 32768
#define DD   512
#define KC   4096
#define LC   3
#define NQ   ((size_t)NPTS * DD)
#define NIDX ((size_t)NPTS * LC)

#define MT 128
#define NTILES 32               // 4096 / 128 cols
#define NCHUNK 128              // 32 tiles * 4 k-chunks
#define MARGIN 8.0f
#define CAND_CAP 128

// smem: A 64KB | B 2x16KB
#define OFF_B 65536
#define SMEM_TOTAL 98304

__device__ float   g_resid[NPTS * DD];
__device__ int8_t  g_ai8[NPTS * DD];
__device__ float   g_sa[NPTS];
__device__ int8_t  g_bi8[LC * KC * DD];
__device__ float   g_sb[LC * KC];
__device__ float   g_c[LC * KC];
__device__ int2    g_cand[NPTS * CAND_CAP];
__device__ int     g_ccnt[NPTS];
__device__ int     g_counts[LC * KC];
__device__ double  g_commit;
__device__ float   g_perp[LC];

__device__ __forceinline__ uint32_t smem_u32(const void* p) {
    uint32_t a;
    asm("{ .reg .u64 t; cvta.to.shared.u64 t, %1; cvt.u32.u64 %0, t; }" : "=r"(a) : "l"(p));
    return a;
}
#define CP_ASYNC16(dst, src) asm volatile("cp.async.cg.shared.global [%0], [%1], 16;" :: "r"(dst), "l"(src))
#define CP_COMMIT() asm volatile("cp.async.commit_group;" ::: "memory")
#define CP_WAIT0()  asm volatile("cp.async.wait_group 0;" ::: "memory")

__device__ __forceinline__ void ldmat4(uint32_t* r, uint32_t addr) {
    asm volatile("ldmatrix.sync.aligned.m8n8.x4.shared.b16 {%0,%1,%2,%3}, [%4];"
        : "=r"(r[0]), "=r"(r[1]), "=r"(r[2]), "=r"(r[3]) : "r"(addr));
}
__device__ __forceinline__ void mma_s8(int* d, const uint32_t* a, const uint32_t* b) {
    asm volatile("mma.sync.aligned.m16n8k32.row.col.s32.s8.s8.s32 "
        "{%0,%1,%2,%3}, {%4,%5,%6,%7}, {%8,%9}, {%0,%1,%2,%3};"
        : "+r"(d[0]), "+r"(d[1]), "+r"(d[2]), "+r"(d[3])
        : "r"(a[0]), "r"(a[1]), "r"(a[2]), "r"(a[3]), "r"(b[0]), "r"(b[1]));
}

__global__ void init_kernel() {
    int i = blockIdx.x * blockDim.x + threadIdx.x;
    if (i < LC * KC) g_counts[i] = 0;
    if (i < NPTS) g_ccnt[i] = 0;
    if (i == 0) g_commit = 0.0;
}

__global__ void quant_z_kernel(const float* __restrict__ z) {
    int row = (blockIdx.x * blockDim.x + threadIdx.x) >> 5;
    int lane = threadIdx.x & 31;
    if (row >= NPTS) return;
    const float4* src = (const float4*)(z + (size_t)row * DD);
    float a[16], amax = 0.f;
    #pragma unroll
    for (int j = 0; j < 4; j++) {
        float4 v = src[j * 32 + lane];
        a[j*4+0] = v.x; a[j*4+1] = v.y; a[j*4+2] = v.z; a[j*4+3] = v.w;
        amax = fmaxf(amax, fmaxf(fmaxf(fabsf(v.x), fabsf(v.y)), fmaxf(fabsf(v.z), fabsf(v.w))));
    }
    #pragma unroll
    for (int o = 16; o; o >>= 1) amax = fmaxf(amax, __shfl_xor_sync(0xffffffffu, amax, o));
    amax = fmaxf(amax, 1e-30f);
    float inv_s = 127.0f / amax;
    #pragma unroll
    for (int j = 0; j < 4; j++) {
        char4 q;
        q.x = (char)__float2int_rn(a[j*4+0] * inv_s);
        q.y = (char)__float2int_rn(a[j*4+1] * inv_s);
        q.z = (char)__float2int_rn(a[j*4+2] * inv_s);
        q.w = (char)__float2int_rn(a[j*4+3] * inv_s);
        *(char4*)(g_ai8 + (size_t)row * DD + (j * 32 + lane) * 4) = q;
    }
    if (lane == 0) g_sa[row] = amax * (1.0f / 127.0f);
}

__global__ void quant_cb_kernel(const float* __restrict__ cb) {
    int row = (blockIdx.x * blockDim.x + threadIdx.x) >> 5;
    int lane = threadIdx.x & 31;
    if (row >= LC * KC) return;
    const float4* src = (const float4*)(cb + (size_t)row * DD);
    float a[16], amax = 0.f, ss = 0.f;
    #pragma unroll
    for (int j = 0; j < 4; j++) {
        float4 v = src[j * 32 + lane];
        a[j*4+0] = v.x; a[j*4+1] = v.y; a[j*4+2] = v.z; a[j*4+3] = v.w;
        amax = fmaxf(amax, fmaxf(fmaxf(fabsf(v.x), fabsf(v.y)), fmaxf(fabsf(v.z), fabsf(v.w))));
        ss += v.x*v.x + v.y*v.y + v.z*v.z + v.w*v.w;
    }
    #pragma unroll
    for (int o = 16; o; o >>= 1) {
        amax = fmaxf(amax, __shfl_xor_sync(0xffffffffu, amax, o));
        ss += __shfl_xor_sync(0xffffffffu, ss, o);
    }
    amax = fmaxf(amax, 1e-30f);
    float inv_s = 127.0f / amax;
    #pragma unroll
    for (int j = 0; j < 4; j++) {
        char4 q;
        q.x = (char)__float2int_rn(a[j*4+0] * inv_s);
        q.y = (char)__float2int_rn(a[j*4+1] * inv_s);
        q.z = (char)__float2int_rn(a[j*4+2] * inv_s);
        q.w = (char)__float2int_rn(a[j*4+3] * inv_s);
        *(char4*)(g_bi8 + (size_t)row * DD + (j * 32 + lane) * 4) = q;
    }
    if (lane == 0) { g_sb[row] = amax * (1.0f / 127.0f); g_c[row] = 0.5f * ss; }
}

// ---- int8 GEMM: CTA = 128 rows x ALL 4096 cols, A resident in smem,
//      register epilogue appends in-margin candidates ----
__global__ __launch_bounds__(256, 2) void gemm_kernel(int layer) {
    extern __shared__ char smem[];
    uint32_t sb = smem_u32(smem);
    int tid = threadIdx.x, wid = tid >> 5, lane = tid & 31;
    int warp_m = wid >> 2, warp_n = wid & 3;     // 2x4 warp grid, 64x32 warp tile
    int m0 = blockIdx.x * MT;
    const int8_t* __restrict__ A = g_ai8;
    const int8_t* __restrict__ B = g_bi8 + (size_t)layer * KC * DD;
    const float* __restrict__ cl = g_c + layer * KC;
    const float* __restrict__ sbl = g_sb + layer * KC;

    // ---- A tile load (once): 4096 units of 16B; swizzled for 512B rows ----
    #pragma unroll
    for (int i = 0; i < 16; i++) {
        int f = tid + i * 256;              // 0..4095
        int r = f >> 5, v = f & 31;
        uint32_t d = (uint32_t)(r * 512 + (((v & 24) | ((v ^ r) & 7)) << 4));
        CP_ASYNC16(sb + d, A + (size_t)(m0 + r) * DD + v * 16);
    }
    CP_COMMIT();

    // ---- B chunk loader precompute: 1024 units per 16KB chunk ----
    const int8_t* bsrc[4]; uint32_t bdst[4];
    #pragma unroll
    for (int i = 0; i < 4; i++) {
        int f = tid + i * 256;              // 0..1023
        int r = f >> 3, v = f & 7;
        bsrc[i] = B + (size_t)r * DD + v * 16;
        bdst[i] = (uint32_t)(r * 128 + ((v ^ (r & 7)) << 4));
    }
    auto load_b = [&](int buf, int j) {
        int off = (j >> 2) * (128 * DD) + (j & 3) * 128;
        uint32_t base = sb + OFF_B + buf * 16384;
        #pragma unroll
        for (int i = 0; i < 4; i++) CP_ASYNC16(base + bdst[i], bsrc[i] + off);
    };
    load_b(0, 0); CP_COMMIT();

    // ---- fragment addressing ----
    int rm = lane & 7;
    int aU = lane >> 4, bU = (lane >> 3) & 1;
    uint32_t aOff[4], bOff[2];
    #pragma unroll
    for (int mi = 0; mi < 4; mi++) aOff[mi] = (uint32_t)((warp_m * 64 + mi * 16 + (lane & 15)) * 512);
    #pragma unroll
    for (int nh = 0; nh < 2; nh++) bOff[nh] = (uint32_t)((warp_n * 32 + nh * 16 + (lane & 7) + ((lane >> 4) << 3)) * 128);

    // per-thread row scales (loop-invariant): hoisted out of the tile loop
    float sar[8];
    #pragma unroll
    for (int s = 0; s < 8; s++)
        sar[s] = __ldg(&g_sa[m0 + warp_m * 64 + (s >> 1) * 16 + (lane >> 2) + (s & 1) * 8]);

    int acc[4][4][4];
    #pragma unroll
    for (int mi = 0; mi < 4; mi++)
        #pragma unroll
        for (int ni = 0; ni < 4; ni++)
            #pragma unroll
            for (int e = 0; e < 4; e++) acc[mi][ni][e] = 0;

    float runmax[8];
    #pragma unroll
    for (int s = 0; s < 8; s++) runmax[s] = -3.0e38f;

    for (int j = 0; j < NCHUNK; j++) {
        CP_WAIT0();
        __syncthreads();
        if (j + 1 < NCHUNK) load_b((j + 1) & 1, j + 1);
        CP_COMMIT();
        uint32_t aC = sb + (uint32_t)((j & 3) * 128);
        uint32_t bB = sb + OFF_B + (uint32_t)((j & 1) * 16384);
        #pragma unroll
        for (int kk = 0; kk < 4; kk++) {
            uint32_t af[4][4], bf[2][4];
            int wA = kk * 2 + aU, wB = kk * 2 + bU;
            #pragma unroll
            for (int mi = 0; mi < 4; mi++)
                ldmat4(af[mi], aC + aOff[mi] + (uint32_t)(((wA ^ rm) & 7) << 4));
            #pragma unroll
            for (int nh = 0; nh < 2; nh++)
                ldmat4(bf[nh], bB + bOff[nh] + (uint32_t)(((wB ^ rm) & 7) << 4));
            #pragma unroll
            for (int mi = 0; mi < 4; mi++) {
                mma_s8(acc[mi][0], af[mi], &bf[0][0]);
                mma_s8(acc[mi][1], af[mi], &bf[0][2]);
                mma_s8(acc[mi][2], af[mi], &bf[1][0]);
                mma_s8(acc[mi][3], af[mi], &bf[1][2]);
            }
        }
        if ((j & 3) == 3) {
            // ---- register epilogue for tile t ----
            int t = j >> 2;
            int cb0 = t * 128 + warp_n * 32 + (lane & 3) * 2;
            float2 sbv[4], csv[4];
            #pragma unroll
            for (int ni = 0; ni < 4; ni++) {
                sbv[ni] = __ldg((const float2*)(sbl + cb0 + ni * 8));
                csv[ni] = __ldg((const float2*)(cl + cb0 + ni * 8));
            }
            float tmax[8];
            #pragma unroll
            for (int s = 0; s < 8; s++) tmax[s] = -3.0e38f;
            #pragma unroll
            for (int mi = 0; mi < 4; mi++)
                #pragma unroll
                for (int ni = 0; ni < 4; ni++)
                    #pragma unroll
                    for (int e = 0; e < 4; e++) {
                        int s = mi * 2 + (e >> 1);
                        float sbp = (e & 1) ? sbv[ni].y : sbv[ni].x;
                        float csp = (e & 1) ? csv[ni].y : csv[ni].x;
                        float sc = fmaf(sar[s] * sbp, (float)acc[mi][ni][e], -csp);
                        acc[mi][ni][e] = __float_as_int(sc);
                        tmax[s] = fmaxf(tmax[s], sc);
                    }
            #pragma unroll
            for (int s = 0; s < 8; s++) {
                tmax[s] = fmaxf(tmax[s], __shfl_xor_sync(0xffffffffu, tmax[s], 1));
                tmax[s] = fmaxf(tmax[s], __shfl_xor_sync(0xffffffffu, tmax[s], 2));
                runmax[s] = fmaxf(runmax[s], tmax[s]);
            }
            #pragma unroll
            for (int mi = 0; mi < 4; mi++)
                #pragma unroll
                for (int ni = 0; ni < 4; ni++)
                    #pragma unroll
                    for (int e = 0; e < 4; e++) {
                        int s = mi * 2 + (e >> 1);
                        float sc = __int_as_float(acc[mi][ni][e]);
                        if (sc >= runmax[s] - MARGIN) {
                            int row = m0 + warp_m * 64 + mi * 16 + (lane >> 2) + (e >> 1) * 8;
                            int col = cb0 + ni * 8 + (e & 1);
                            int slot = atomicAdd(&g_ccnt[row], 1);
                            if (slot < CAND_CAP)
                                g_cand[row * CAND_CAP + slot] = make_int2(col, __float_as_int(sc));
                        }
                        acc[mi][ni][e] = 0;
                    }
        }
    }
}

// ---- fused exact re-rank + assign + next-layer quantize (warp per row) ----
template <bool LAST>
__global__ __launch_bounds__(128) void rerank_assign_kernel(
    const float* __restrict__ z, const float* __restrict__ cb,
    float* __restrict__ out_q, float* __restrict__ out_idx, int layer)
{
    int warp = (blockIdx.x * blockDim.x + threadIdx.x) >> 5;
    int lane = threadIdx.x & 31;
    if (warp >= NPTS) return;
    int row = warp;
    const float* Ar = (layer == 0) ? z + (size_t)row * DD : g_resid + (size_t)row * DD;
    const float* El = cb + (size_t)layer * KC * DD;
    const float* cl = g_c + layer * KC;

    int cnt = g_ccnt[row];
    if (lane == 0) g_ccnt[row] = 0;    // reset for next layer

    float a[16];
    #pragma unroll
    for (int j = 0; j < 4; j++) {
        float4 v = ((const float4*)Ar)[j * 32 + lane];
        a[j*4+0] = v.x; a[j*4+1] = v.y; a[j*4+2] = v.z; a[j*4+3] = v.w;
    }

    float bs = -3.0e38f; int bi = 0x7fffffff;
    auto eval = [&](int k) {
        const float4* E4 = (const float4*)(El + (size_t)k * DD);
        float s = 0.f;
        #pragma unroll
        for (int j = 0; j < 4; j++) {
            float4 e = E4[j * 32 + lane];
            s = fmaf(a[j*4+0], e.x, s); s = fmaf(a[j*4+1], e.y, s);
            s = fmaf(a[j*4+2], e.z, s); s = fmaf(a[j*4+3], e.w, s);
        }
        #pragma unroll
        for (int o = 16; o; o >>= 1) s += __shfl_xor_sync(0xffffffffu, s, o);
        s -= cl[k];
        if (s > bs || (s == bs && k < bi)) { bs = s; bi = k; }
    };

    if (cnt > CAND_CAP) {
        for (int k = 0; k < KC; k++) eval(k);
    } else {
        // up to 128 candidates, 4 per lane
        int2 cd[4];
        float sc[4];
        #pragma unroll
        for (int c = 0; c < 4; c++) {
            int idx = c * 32 + lane;
            cd[c] = (idx < cnt) ? g_cand[row * CAND_CAP + idx]
                                : make_int2(0, (int)0xff800000u);
            sc[c] = __int_as_float(cd[c].y);
        }
        float cmax = fmaxf(fmaxf(sc[0], sc[1]), fmaxf(sc[2], sc[3]));
        #pragma unroll
        for (int o = 16; o; o >>= 1) cmax = fmaxf(cmax, __shfl_xor_sync(0xffffffffu, cmax, o));
        float thr = cmax - MARGIN;
        unsigned msk[4];
        int tot = 0;
        #pragma unroll
        for (int c = 0; c < 4; c++) {
            msk[c] = __ballot_sync(0xffffffffu, sc[c] >= thr);
            tot += __popc(msk[c]);
        }
        if (tot == 1) {
            #pragma unroll
            for (int c = 0; c < 4; c++)
                if (msk[c]) bi = __shfl_sync(0xffffffffu, cd[c].x, __ffs(msk[c]) - 1);
        } else {
            #pragma unroll
            for (int c = 0; c < 4; c++) {
                unsigned m = msk[c];
                while (m) {
                    int t = __ffs(m) - 1; m &= m - 1;
                    eval(__shfl_sync(0xffffffffu, cd[c].x, t));
                }
            }
        }
    }

    if (lane == 0) {
        out_idx[(size_t)row * LC + layer] = (float)bi;
        atomicAdd(&g_counts[layer * KC + bi], 1);
    }
    const float4* E4 = (const float4*)(El + (size_t)bi * DD);
    float csum = 0.f;
    float rn[16], amax = 0.f;
    #pragma unroll
    for (int j = 0; j < 4; j++) {
        float4 e = E4[j * 32 + lane];
        rn[j*4+0] = a[j*4+0] - e.x; rn[j*4+1] = a[j*4+1] - e.y;
        rn[j*4+2] = a[j*4+2] - e.z; rn[j*4+3] = a[j*4+3] - e.w;
        #pragma unroll
        for (int e2 = 0; e2 < 4; e2++) {
            csum += rn[j*4+e2] * rn[j*4+e2];
            amax = fmaxf(amax, fabsf(rn[j*4+e2]));
        }
        if (LAST) {
            float4 zv = ((const float4*)(z + (size_t)row * DD))[j * 32 + lane];
            ((float4*)(out_q + (size_t)row * DD))[j * 32 + lane] =
                make_float4(zv.x - rn[j*4+0], zv.y - rn[j*4+1], zv.z - rn[j*4+2], zv.w - rn[j*4+3]);
        } else {
            ((float4*)(g_resid + (size_t)row * DD))[j * 32 + lane] =
                make_float4(rn[j*4+0], rn[j*4+1], rn[j*4+2], rn[j*4+3]);
        }
    }
    if (!LAST) {
        #pragma unroll
        for (int o = 16; o; o >>= 1) amax = fmaxf(amax, __shfl_xor_sync(0xffffffffu, amax, o));
        amax = fmaxf(amax, 1e-30f);
        float inv_s = 127.0f / amax;
        #pragma unroll
        for (int j = 0; j < 4; j++) {
            char4 q;
            q.x = (char)__float2int_rn(rn[j*4+0] * inv_s);
            q.y = (char)__float2int_rn(rn[j*4+1] * inv_s);
            q.z = (char)__float2int_rn(rn[j*4+2] * inv_s);
            q.w = (char)__float2int_rn(rn[j*4+3] * inv_s);
            *(char4*)(g_ai8 + (size_t)row * DD + (j * 32 + lane) * 4) = q;
        }
        if (lane == 0) g_sa[row] = amax * (1.0f / 127.0f);
    }
    #pragma unroll
    for (int o = 16; o; o >>= 1) csum += __shfl_down_sync(0xffffffffu, csum, o);
    if (lane == 0) atomicAdd(&g_commit, (double)csum);
}

__global__ void perp_kernel() {
    int l = blockIdx.x, t = threadIdx.x;
    float local = 0.f;
    for (int k = t; k < KC; k += 256) {
        float p = (float)g_counts[l * KC + k] * (1.0f / (float)NPTS);
        local += p * logf(p + 1e-10f);
    }
    #pragma unroll
    for (int o = 16; o; o >>= 1) local += __shfl_down_sync(0xffffffffu, local, o);
    __shared__ float red[8];
    if ((t & 31) == 0) red[t >> 5] = local;
    __syncthreads();
    if (t == 0) {
        float s = 0.f;
        #pragma unroll
        for (int i = 0; i < 8; i++) s += red[i];
        g_perp[l] = expf(-s);
    }
}
__global__ void final_kernel(float* __restrict__ out_sc) {
    out_sc[0] = (float)(g_commit * (0.25 / (double)NQ));
    out_sc[1] = (g_perp[0] + g_perp[1] + g_perp[2]) * (1.0f / 3.0f);
}

extern "C" void kernel_launch(void* const* d_in, const int* in_sizes, int n_in,
                              void* d_out, int out_size)
{
    const float* z  = (const float*)d_in[0];
    const float* cb = (const float*)d_in[1];
    float* out = (float*)d_out;
    float* out_q   = out;
    float* out_idx = out + NQ;
    float* out_sc  = out_idx + NIDX;

    cudaFuncSetAttribute(gemm_kernel, cudaFuncAttributeMaxDynamicSharedMemorySize, SMEM_TOTAL);

    init_kernel<<<160, 256>>>();
    quant_z_kernel<<<NPTS / 8, 256>>>(z);
    quant_cb_kernel<<<(LC * KC) / 8, 256>>>(cb);

    for (int l = 0; l < LC; l++) {
        gemm_kernel<<<NPTS / MT, 256, SMEM_TOTAL>>>(l);
        if (l < LC - 1)
            rerank_assign_kernel<false><<<NPTS / 4, 128>>>(z, cb, out_q, out_idx, l);
        else
            rerank_assign_kernel<true><<<NPTS / 4, 128>>>(z, cb, out_q, out_idx, l);
    }
    perp_kernel<<<LC, 256>>>();
    final_kernel<<<1, 1>>>(out_sc);
}